// round 16
// baseline (speedup 1.0000x reference)
#include <cuda_runtime.h>
#include <cuda_bf16.h>
#include <cstdint>

#define G 8
#define THREADS 256
#define NBLK (8192 / G)

// Sign matrices (+-1 bf16, zero-padded) and per-tensor scales.
__device__ __align__(16) __nv_bfloat16 g_s1c[8 * 128];         // conv1 signs [ch8][16 combos x 8 taps]
__device__ __align__(16) __nv_bfloat16 g_s2bf[16 * 240];       // conv2 signs [ch][30 combos x 8 taps]
__device__ __align__(16) __nv_bfloat16 g_s1bf[120 * 400];      // fc1 signs [j][k]
__device__ float g_cs1, g_cs2;                                 // conv scales
__device__ float g_fscale[3];                                  // fc1, fc2, fc3 scales

__global__ void binarize_kernel(const float* __restrict__ w1,
                                const float* __restrict__ w2,
                                const float* __restrict__ fw1,
                                const float* __restrict__ fw2,
                                const float* __restrict__ fw3) {
    __shared__ float red[256];
    int t = threadIdx.x;
    const float* src = nullptr;
    int n = 0;
    switch (blockIdx.x) {
        case 0: src = w1;  n = 450;   break;
        case 1: src = w2;  n = 2400;  break;
        case 2: src = fw1; n = 48000; break;
        case 3: src = fw2; n = 10080; break;
        case 4: src = fw3; n = 840;   break;
    }
    float s = 0.0f;
    for (int i = t; i < n; i += 256) s += fabsf(src[i]);
    red[t] = s;
    __syncthreads();
    for (int o = 128; o > 0; o >>= 1) {
        if (t < o) red[t] += red[t + o];
        __syncthreads();
    }
    float scale = red[0] / (float)n;

    switch (blockIdx.x) {
        case 0:  // conv1 signs [ch][ (cin*5+ky)*8 + kx ]; pads stay 0
            for (int i = t; i < n; i += 256) {
                int o = i / 75, rem = i % 75, cin = rem / 25, kk = rem % 25;
                int ky = kk / 5, kx = kk % 5;
                g_s1c[o * 128 + (cin * 5 + ky) * 8 + kx] =
                    __float2bfloat16((src[i] >= 0.0f) ? 1.0f : -1.0f);
            }
            if (t == 0) g_cs1 = scale;
            break;
        case 1:  // conv2 signs [ch][ (cin*5+ky)*8 + kx ]
            for (int i = t; i < n; i += 256) {
                int o = i / 150, rem = i % 150, cin = rem / 25, kk = rem % 25;
                int ky = kk / 5, kx = kk % 5;
                g_s2bf[o * 240 + (cin * 5 + ky) * 8 + kx] =
                    __float2bfloat16((src[i] >= 0.0f) ? 1.0f : -1.0f);
            }
            if (t == 0) g_cs2 = scale;
            break;
        case 2:  // fc1 signs [j][k]
            for (int i = t; i < n; i += 256)
                g_s1bf[i] = __float2bfloat16((src[i] >= 0.0f) ? 1.0f : -1.0f);
            if (t == 0) g_fscale[0] = scale;
            break;
        case 3: if (t == 0) g_fscale[1] = scale; break;
        case 4: if (t == 0) g_fscale[2] = scale; break;
    }
}

extern __shared__ float smem[];

__device__ __forceinline__ void mma_bf16(float* d, uint32_t a0, uint32_t a1,
                                         uint32_t a2, uint32_t a3,
                                         uint32_t b0, uint32_t b1) {
    asm volatile(
        "mma.sync.aligned.m16n8k16.row.col.f32.bf16.bf16.f32 "
        "{%0,%1,%2,%3}, {%4,%5,%6,%7}, {%8,%9}, {%0,%1,%2,%3};"
        : "+f"(d[0]), "+f"(d[1]), "+f"(d[2]), "+f"(d[3])
        : "r"(a0), "r"(a1), "r"(a2), "r"(a3), "r"(b0), "r"(b1));
}

__device__ __forceinline__ uint32_t prmt5432(uint32_t a, uint32_t b) {
    uint32_t r;
    asm("prmt.b32 %0, %1, %2, 0x5432;" : "=r"(r) : "r"(a), "r"(b));
    return r;
}

__device__ __forceinline__ void split_store(__nv_bfloat16* hi, __nv_bfloat16* lo,
                                            int idx, float v) {
    __nv_bfloat16 h = __float2bfloat16(v);
    hi[idx] = h;
    lo[idx] = __float2bfloat16(v - __bfloat162float(h));
}

__global__ void __launch_bounds__(THREADS, 3)
fused_kernel(const float* __restrict__ x,
             const float* __restrict__ fw2, const float* __restrict__ fw3,
             const float* __restrict__ b1, const float* __restrict__ b2,
             const float* __restrict__ fb1, const float* __restrict__ fb2,
             const float* __restrict__ fb3,
             float* __restrict__ out) {
    // smem layout (floats). xs (conv1 staging) ALIASES [a1..h2lo] (used later).
    float* const a1   = smem;                 // 960   [img][120]
    float* const a2v  = a1 + 960;             // 672   [img][84]
    float* const h2hi = a2v + 672;            // 1600 (= 3200 bf16 [img][400])
    float* const h2lo = h2hi + 1600;          // 1600
    float* const p1hi = h2lo + 1600;          // 6048 (= 12096 bf16 [img][c6][14][18])
    float* const p1lo = p1hi + 6048;          // 6048
    float* const b1s  = p1lo + 6048;          // 8
    float* const b2s  = b1s + 8;              // 16
    // total 16952 floats = 67,808 B

    __nv_bfloat16* const xs_hi_b = (__nv_bfloat16*)smem;     // [3][32][36] bf16
    __nv_bfloat16* const xs_lo_b = xs_hi_b + 3456;
    const uint32_t* const xs_hi_u = (const uint32_t*)smem;   // u32 view
    const uint32_t* const xs_lo_u = xs_hi_u + 1728;

    __nv_bfloat16* const p1hi_b = (__nv_bfloat16*)p1hi;
    __nv_bfloat16* const p1lo_b = (__nv_bfloat16*)p1lo;
    __nv_bfloat16* const h2hi_b = (__nv_bfloat16*)h2hi;
    __nv_bfloat16* const h2lo_b = (__nv_bfloat16*)h2lo;
    const uint32_t* const p1hi_u = (const uint32_t*)p1hi;
    const uint32_t* const p1lo_u = (const uint32_t*)p1lo;
    const uint32_t* const h2hi_u = (const uint32_t*)h2hi;
    const uint32_t* const h2lo_u = (const uint32_t*)h2lo;
    uint32_t* const p1hi_w = (uint32_t*)p1hi;
    uint32_t* const p1lo_w = (uint32_t*)p1lo;

    const int tid = threadIdx.x;
    const int wid = tid >> 5, lane = tid & 31;
    const int tq = lane >> 2, tr = lane & 3;
    const int img0 = blockIdx.x * G;

    if (tid < 6)  b1s[tid] = b1[tid];
    if (tid < 16) b2s[tid] = b2[tid];
    // zero p1 pad cols 14..17
    for (int i = tid; i < 672; i += THREADS) {
        p1hi_w[i * 9 + 7] = 0u; p1hi_w[i * 9 + 8] = 0u;
        p1lo_w[i * 9 + 7] = 0u; p1lo_w[i * 9 + 8] = 0u;
    }
    __syncthreads();

    // ================= conv1 + relu + pool via MMA, per image =================
    const uint32_t* s1u = (const uint32_t*)g_s1c;   // [ch8][64 u32]
    for (int g = 0; g < G; g++) {
        // ---- stage image g as bf16 hi/lo [cin][32][36], pads zeroed ----
        const float* xg = x + (size_t)(img0 + g) * 3072;
        for (int i = tid; i < 3072; i += THREADS) {
            int cin = i >> 10, rem = i & 1023;      // [cin][y*32+col]
            int y = rem >> 5, col = rem & 31;
            int idx = (cin * 32 + y) * 36 + col;
            split_store(xs_hi_b, xs_lo_b, idx, xg[i]);
        }
        for (int i = tid; i < 384; i += THREADS) {  // pad cols 32..35
            int row = i >> 2, col = 32 + (i & 3);
            int idx = row * 36 + col;
            xs_hi_b[idx] = __float2bfloat16(0.0f);
            xs_lo_b[idx] = __float2bfloat16(0.0f);
        }
        __syncthreads();

        // ---- 25 tiles of 8 pooled positions ----
        for (int t = wid; t < 25; t += 8) {
            int pt = t * 8 + tq;                    // this thread's pooled pos
            int ptc = (pt < 196) ? pt : 0;
            int Y = ptc / 14, X = ptc % 14;
            float de[4] = {0, 0, 0, 0}, dz[4] = {0, 0, 0, 0};
            int ce = 2 * X + 2 * tr;                // even col base (even)

            #pragma unroll
            for (int kb = 0; kb < 8; kb++) {
                const int c0 = 2 * kb, c1 = 2 * kb + 1;
                const int cin0 = c0 / 5, ky0 = c0 % 5;
                const int cin1 = (c1 < 15) ? c1 / 5 : 0;
                const int ky1  = (c1 < 15) ? c1 % 5 : 0;
                // B: signs, col = channel = tq
                uint32_t B0 = __ldg(s1u + tq * 64 + kb * 8 + tr);
                uint32_t B1 = __ldg(s1u + tq * 64 + kb * 8 + tr + 4);

                int r00 = (cin0 * 32 + 2 * Y + ky0) * 36;      // dy=0, c0
                int r01 = r00 + 36;                             // dy=1, c0
                int r10 = (cin1 * 32 + 2 * Y + ky1) * 36;      // dy=0, c1
                int r11 = r10 + 36;                             // dy=1, c1

                uint32_t h00 = xs_hi_u[(r00 + ce) >> 1];
                uint32_t h01 = xs_hi_u[(r01 + ce) >> 1];
                uint32_t h10 = xs_hi_u[(r10 + ce) >> 1];
                uint32_t h11 = xs_hi_u[(r11 + ce) >> 1];
                uint32_t l00 = xs_lo_u[(r00 + ce) >> 1];
                uint32_t l01 = xs_lo_u[(r01 + ce) >> 1];
                uint32_t l10 = xs_lo_u[(r10 + ce) >> 1];
                uint32_t l11 = xs_lo_u[(r11 + ce) >> 1];
                mma_bf16(de, h00, h01, h10, h11, B0, B1);
                mma_bf16(de, l00, l01, l10, l11, B0, B1);

                uint32_t n00 = xs_hi_u[((r00 + ce) >> 1) + 1];
                uint32_t n01 = xs_hi_u[((r01 + ce) >> 1) + 1];
                uint32_t n10 = xs_hi_u[((r10 + ce) >> 1) + 1];
                uint32_t n11 = xs_hi_u[((r11 + ce) >> 1) + 1];
                uint32_t m00 = xs_lo_u[((r00 + ce) >> 1) + 1];
                uint32_t m01 = xs_lo_u[((r01 + ce) >> 1) + 1];
                uint32_t m10 = xs_lo_u[((r10 + ce) >> 1) + 1];
                uint32_t m11 = xs_lo_u[((r11 + ce) >> 1) + 1];
                mma_bf16(dz, prmt5432(h00, n00), prmt5432(h01, n01),
                             prmt5432(h10, n10), prmt5432(h11, n11), B0, B1);
                mma_bf16(dz, prmt5432(l00, m00), prmt5432(l01, m01),
                             prmt5432(l10, m10), prmt5432(l11, m11), B0, B1);
            }

            // epilogue: rows tq(dy0)/tq+8(dy1) are the vertical pool pair;
            // even/odd tiles are the horizontal pair. cols 2tr,2tr+1 = channels.
            if (pt < 196 && tr < 3) {
                float sc = g_cs1;
                int ch0 = 2 * tr, ch1 = 2 * tr + 1;
                float m0 = fmaxf(fmaxf(de[0], de[2]), fmaxf(dz[0], dz[2]));
                float m1 = fmaxf(fmaxf(de[1], de[3]), fmaxf(dz[1], dz[3]));
                float v0 = fmaxf(fmaf(sc, m0, b1s[ch0]), 0.0f);
                float v1 = fmaxf(fmaf(sc, m1, b1s[ch1]), 0.0f);
                split_store(p1hi_b, p1lo_b, ((g * 6 + ch0) * 14 + Y) * 18 + X, v0);
                split_store(p1hi_b, p1lo_b, ((g * 6 + ch1) * 14 + Y) * 18 + X, v1);
            }
        }
        __syncthreads();
    }

    // ================= conv2 + relu + pool via MMA (as R15) =================
    {
        const uint32_t* s2u = (const uint32_t*)g_s2bf;   // [ch][120 u32]
        for (int u = wid; u < 56; u += 8) {
            int img = u / 7, tp = u % 7;
            float de[4] = {0, 0, 0, 0}, dz[4] = {0, 0, 0, 0};

            int v = tp * 8 + tq;
            int q = v >> 1, dy = v & 1;
            if (q >= 25) { q = 0; dy = 0; }
            int Y = q / 5, X = q % 5;
            int oy = 2 * Y + dy;
            int oxe = 2 * X;

            #pragma unroll
            for (int ks = 0; ks < 15; ks++) {
                const int m0 = 2 * ks, m1 = 2 * ks + 1;
                const int cin0 = m0 / 5, ky0 = m0 % 5;
                const int cin1 = m1 / 5, ky1 = m1 % 5;
                uint32_t A0 = __ldg(s2u + tq * 120 + ks * 8 + tr);
                uint32_t A1 = __ldg(s2u + (tq + 8) * 120 + ks * 8 + tr);
                uint32_t A2 = __ldg(s2u + tq * 120 + ks * 8 + tr + 4);
                uint32_t A3 = __ldg(s2u + (tq + 8) * 120 + ks * 8 + tr + 4);

                int r0 = ((img * 6 + cin0) * 14 + (oy + ky0)) * 18;
                int r1 = ((img * 6 + cin1) * 14 + (oy + ky1)) * 18;
                int ce = oxe + 2 * tr;
                uint32_t e0h = p1hi_u[(r0 + ce) >> 1];
                uint32_t e1h = p1hi_u[(r1 + ce) >> 1];
                uint32_t e0l = p1lo_u[(r0 + ce) >> 1];
                uint32_t e1l = p1lo_u[(r1 + ce) >> 1];
                mma_bf16(de, A0, A1, A2, A3, e0h, e1h);
                mma_bf16(de, A0, A1, A2, A3, e0l, e1l);
                uint32_t x0h = p1hi_u[((r0 + ce) >> 1) + 1];
                uint32_t x1h = p1hi_u[((r1 + ce) >> 1) + 1];
                uint32_t x0l = p1lo_u[((r0 + ce) >> 1) + 1];
                uint32_t x1l = p1lo_u[((r1 + ce) >> 1) + 1];
                mma_bf16(dz, A0, A1, A2, A3, prmt5432(e0h, x0h), prmt5432(e1h, x1h));
                mma_bf16(dz, A0, A1, A2, A3, prmt5432(e0l, x0l), prmt5432(e1l, x1l));
            }

            int qq = tp * 4 + tr;
            if (qq < 25) {
                float sc = g_cs2;
                float m0 = fmaxf(fmaxf(de[0], de[1]), fmaxf(dz[0], dz[1]));
                float m1 = fmaxf(fmaxf(de[2], de[3]), fmaxf(dz[2], dz[3]));
                float h0 = fmaxf(fmaf(sc, m0, b2s[tq]), 0.0f);
                float h1 = fmaxf(fmaf(sc, m1, b2s[tq + 8]), 0.0f);
                split_store(h2hi_b, h2lo_b, img * 400 + tq * 25 + qq, h0);
                split_store(h2hi_b, h2lo_b, img * 400 + (tq + 8) * 25 + qq, h1);
            }
        }
    }
    __syncthreads();

    // ================= fc1 via MMA (as R15) =================
    {
        const uint32_t* s1fu = (const uint32_t*)g_s1bf;   // [j][200 u32]
        for (int nt = wid; nt < 15; nt += 8) {
            float d[4] = {0, 0, 0, 0};
            int j = nt * 8 + tq;
            #pragma unroll 5
            for (int ks = 0; ks < 25; ks++) {
                uint32_t a0 = h2hi_u[tq * 200 + ks * 8 + tr];
                uint32_t a2 = h2hi_u[tq * 200 + ks * 8 + tr + 4];
                uint32_t l0 = h2lo_u[tq * 200 + ks * 8 + tr];
                uint32_t l2 = h2lo_u[tq * 200 + ks * 8 + tr + 4];
                uint32_t B0 = __ldg(s1fu + j * 200 + ks * 8 + tr);
                uint32_t B1 = __ldg(s1fu + j * 200 + ks * 8 + tr + 4);
                mma_bf16(d, a0, 0u, a2, 0u, B0, B1);
                mma_bf16(d, l0, 0u, l2, 0u, B0, B1);
            }
            int jc = nt * 8 + 2 * tr;
            float sc = g_fscale[0];
            a1[tq * 120 + jc]     = fmaxf(fmaf(sc, d[0], __ldg(fb1 + jc)), 0.0f);
            a1[tq * 120 + jc + 1] = fmaxf(fmaf(sc, d[1], __ldg(fb1 + jc + 1)), 0.0f);
        }
    }
    __syncthreads();

    // ================= fc2 scalar XOR =================
    if (tid < 168) {
        int half = tid & 1, j = tid >> 1;
        const float* hg = a1 + half * 4 * 120;
        const float* wr = fw2 + j * 120;
        float acc[4] = {0, 0, 0, 0};
        for (int k = 0; k < 120; k += 4) {
            float4 w = __ldg((const float4*)(wr + k));
            unsigned sx = __float_as_uint(w.x) & 0x80000000u;
            unsigned sy = __float_as_uint(w.y) & 0x80000000u;
            unsigned sz = __float_as_uint(w.z) & 0x80000000u;
            unsigned sw = __float_as_uint(w.w) & 0x80000000u;
            #pragma unroll
            for (int i = 0; i < 4; i++) {
                float4 h = *(const float4*)(hg + i * 120 + k);
                acc[i] += __uint_as_float(__float_as_uint(h.x) ^ sx);
                acc[i] += __uint_as_float(__float_as_uint(h.y) ^ sy);
                acc[i] += __uint_as_float(__float_as_uint(h.z) ^ sz);
                acc[i] += __uint_as_float(__float_as_uint(h.w) ^ sw);
            }
        }
        float sc = g_fscale[1];
        float bb = fb2[j];
        #pragma unroll
        for (int i = 0; i < 4; i++)
            a2v[(half * 4 + i) * 84 + j] = fmaxf(fmaf(sc, acc[i], bb), 0.0f);
    }
    __syncthreads();

    // ================= fc3 scalar XOR =================
    if (tid < G * 10) {
        int g = tid / 10, j = tid % 10;
        const float* ag = a2v + g * 84;
        const float* wr = fw3 + j * 84;
        float acc = 0.0f;
        for (int k = 0; k < 84; k += 4) {
            float4 w = __ldg((const float4*)(wr + k));
            float4 h = *(const float4*)(ag + k);
            acc += __uint_as_float(__float_as_uint(h.x) ^ (__float_as_uint(w.x) & 0x80000000u));
            acc += __uint_as_float(__float_as_uint(h.y) ^ (__float_as_uint(w.y) & 0x80000000u));
            acc += __uint_as_float(__float_as_uint(h.z) ^ (__float_as_uint(w.z) & 0x80000000u));
            acc += __uint_as_float(__float_as_uint(h.w) ^ (__float_as_uint(w.w) & 0x80000000u));
        }
        out[(size_t)(img0 + g) * 10 + j] = fmaf(g_fscale[2], acc, fb3[j]);
    }
}

extern "C" void kernel_launch(void* const* d_in, const int* in_sizes, int n_in,
                              void* d_out, int out_size) {
    const float* x   = (const float*)d_in[0];
    const float* w1  = (const float*)d_in[1];
    const float* b1  = (const float*)d_in[2];
    const float* w2  = (const float*)d_in[3];
    const float* b2  = (const float*)d_in[4];
    const float* fw1 = (const float*)d_in[5];
    const float* fb1 = (const float*)d_in[6];
    const float* fw2 = (const float*)d_in[7];
    const float* fb2 = (const float*)d_in[8];
    const float* fw3 = (const float*)d_in[9];
    const float* fb3 = (const float*)d_in[10];
    float* out = (float*)d_out;

    // smem: 960+672+1600+1600+6048+6048+8+16 = 16952 floats = 67,808 B
    const int smem_bytes = 16952 * (int)sizeof(float);
    cudaFuncSetAttribute(fused_kernel, cudaFuncAttributeMaxDynamicSharedMemorySize,
                         smem_bytes);

    binarize_kernel<<<5, 256>>>(w1, w2, fw1, fw2, fw3);
    fused_kernel<<<NBLK, THREADS, smem_bytes>>>(x, fw2, fw3,
                                                b1, b2, fb1, fb2, fb3, out);
}

// round 17
// speedup vs baseline: 1.1796x; 1.1796x over previous
#include <cuda_runtime.h>
#include <cuda_bf16.h>
#include <cstdint>

#define G 8
#define THREADS 256
#define NBLK (8192 / G)

// conv1 weights (+-scale baked) [cg][cin][k][4] (3 used); sign matrices; scales.
__device__ __align__(16) float g_w1c[2 * 3 * 25 * 4];          // [cg][cin][k][c4]
__device__ __align__(16) __nv_bfloat16 g_s2bf[16 * 240];       // conv2 signs [ch][30 combos x 8 taps]
__device__ __align__(16) __nv_bfloat16 g_s1bf[120 * 400];      // fc1 signs [j][k]
__device__ float g_cs2;                                        // conv2 scale
__device__ float g_fscale[3];                                  // fc1, fc2, fc3 scales

__global__ void binarize_kernel(const float* __restrict__ w1,
                                const float* __restrict__ w2,
                                const float* __restrict__ fw1,
                                const float* __restrict__ fw2,
                                const float* __restrict__ fw3) {
    __shared__ float red[256];
    int t = threadIdx.x;
    const float* src = nullptr;
    int n = 0;
    switch (blockIdx.x) {
        case 0: src = w1;  n = 450;   break;
        case 1: src = w2;  n = 2400;  break;
        case 2: src = fw1; n = 48000; break;
        case 3: src = fw2; n = 10080; break;
        case 4: src = fw3; n = 840;   break;
    }
    float s = 0.0f;
    for (int i = t; i < n; i += 256) s += fabsf(src[i]);
    red[t] = s;
    __syncthreads();
    for (int o = 128; o > 0; o >>= 1) {
        if (t < o) red[t] += red[t + o];
        __syncthreads();
    }
    float scale = red[0] / (float)n;

    switch (blockIdx.x) {
        case 0:  // w1[o][cin][5][5] -> [cg][cin][k][4], +-scale baked, pad 0
            for (int i = t; i < n; i += 256) {
                int o = i / 75, rem = i % 75, cin = rem / 25, k = rem % 25;
                int cg = o / 3, cl = o % 3;
                g_w1c[((cg * 3 + cin) * 25 + k) * 4 + cl] =
                    (src[i] >= 0.0f) ? scale : -scale;
            }
            break;
        case 1:  // conv2 signs: [ch][ (cin*5+ky)*8 + kx ], +-1 (taps 5..7 stay 0)
            for (int i = t; i < n; i += 256) {
                int o = i / 150, rem = i % 150, cin = rem / 25, kk = rem % 25;
                int ky = kk / 5, kx = kk % 5;
                g_s2bf[o * 240 + (cin * 5 + ky) * 8 + kx] =
                    __float2bfloat16((src[i] >= 0.0f) ? 1.0f : -1.0f);
            }
            if (t == 0) g_cs2 = scale;
            break;
        case 2:  // fc1 signs [j][k]
            for (int i = t; i < n; i += 256)
                g_s1bf[i] = __float2bfloat16((src[i] >= 0.0f) ? 1.0f : -1.0f);
            if (t == 0) g_fscale[0] = scale;
            break;
        case 3: if (t == 0) g_fscale[1] = scale; break;
        case 4: if (t == 0) g_fscale[2] = scale; break;
    }
}

extern __shared__ float smem[];

// One ky-row for 3 channels over an 8-wide window (4 conv cols x 2 rows).
#define C1KY8(TOP, BOT, KY)                                                    \
    {                                                                          \
        _Pragma("unroll")                                                      \
        for (int kx = 0; kx < 5; kx++) {                                       \
            float4 wv = *(const float4*)(wb + ((KY) * 5 + kx) * 4);            \
            float wc[3] = {wv.x, wv.y, wv.z};                                  \
            _Pragma("unroll")                                                  \
            for (int c = 0; c < 3; c++)                                        \
                _Pragma("unroll")                                              \
                for (int j = 0; j < 4; j++) {                                  \
                    acc[c][0][j] = fmaf(wc[c], TOP[kx + j], acc[c][0][j]);     \
                    acc[c][1][j] = fmaf(wc[c], BOT[kx + j], acc[c][1][j]);     \
                }                                                              \
        }                                                                      \
    }

#define LOAD_ROW8(DST, PTR)                                                    \
    {                                                                          \
        float4 va = __ldg((const float4*)(PTR));                               \
        float4 vb = __ldg((const float4*)((PTR) + 4));                         \
        DST[0] = va.x; DST[1] = va.y; DST[2] = va.z; DST[3] = va.w;            \
        DST[4] = vb.x; DST[5] = vb.y; DST[6] = vb.z; DST[7] = vb.w;            \
    }

__device__ __forceinline__ void mma_bf16(float* d, uint32_t a0, uint32_t a1,
                                         uint32_t a2, uint32_t a3,
                                         uint32_t b0, uint32_t b1) {
    asm volatile(
        "mma.sync.aligned.m16n8k16.row.col.f32.bf16.bf16.f32 "
        "{%0,%1,%2,%3}, {%4,%5,%6,%7}, {%8,%9}, {%0,%1,%2,%3};"
        : "+f"(d[0]), "+f"(d[1]), "+f"(d[2]), "+f"(d[3])
        : "r"(a0), "r"(a1), "r"(a2), "r"(a3), "r"(b0), "r"(b1));
}

__device__ __forceinline__ uint32_t prmt5432(uint32_t a, uint32_t b) {
    uint32_t r;
    asm("prmt.b32 %0, %1, %2, 0x5432;" : "=r"(r) : "r"(a), "r"(b));
    return r;
}

__device__ __forceinline__ void split_store(__nv_bfloat16* hi, __nv_bfloat16* lo,
                                            int idx, float v) {
    __nv_bfloat16 h = __float2bfloat16(v);
    hi[idx] = h;
    lo[idx] = __float2bfloat16(v - __bfloat162float(h));
}

__global__ void __launch_bounds__(THREADS, 3)
fused_kernel(const float* __restrict__ x,
             const float* __restrict__ fw2, const float* __restrict__ fw3,
             const float* __restrict__ b1, const float* __restrict__ b2,
             const float* __restrict__ fb1, const float* __restrict__ fb2,
             const float* __restrict__ fb3,
             float* __restrict__ out) {
    // smem layout (floats)
    float* const a1   = smem;                 // 960   [img][120]
    float* const a2v  = a1 + 960;             // 672   [img][84]
    float* const w1s  = a2v + 672;            // 600   [cg][cin][k][4]
    float* const b1s  = w1s + 600;            // 8
    float* const b2s  = b1s + 8;              // 16
    float* const h2hi = b2s + 16;             // 1600 (= 3200 bf16 [img][400])
    float* const h2lo = h2hi + 1600;          // 1600
    float* const p1hi = h2lo + 1600;          // 6048 (= 12096 bf16 [img][c6][14][18])
    float* const p1lo = p1hi + 6048;          // 6048

    __nv_bfloat16* const p1hi_b = (__nv_bfloat16*)p1hi;
    __nv_bfloat16* const p1lo_b = (__nv_bfloat16*)p1lo;
    __nv_bfloat16* const h2hi_b = (__nv_bfloat16*)h2hi;
    __nv_bfloat16* const h2lo_b = (__nv_bfloat16*)h2lo;
    const uint32_t* const p1hi_u = (const uint32_t*)p1hi;
    const uint32_t* const p1lo_u = (const uint32_t*)p1lo;
    const uint32_t* const h2hi_u = (const uint32_t*)h2hi;
    const uint32_t* const h2lo_u = (const uint32_t*)h2lo;
    uint32_t* const p1hi_w = (uint32_t*)p1hi;
    uint32_t* const p1lo_w = (uint32_t*)p1lo;

    const int tid = threadIdx.x;
    const int img0 = blockIdx.x * G;

    for (int i = tid; i < 600; i += THREADS) w1s[i] = g_w1c[i];
    if (tid < 6)  b1s[tid] = b1[tid];
    if (tid < 16) b2s[tid] = b2[tid];
    // zero p1 pad cols 14..17
    for (int i = tid; i < 672; i += THREADS) {
        p1hi_w[i * 9 + 7] = 0u; p1hi_w[i * 9 + 8] = 0u;
        p1lo_w[i * 9 + 7] = 0u; p1lo_w[i * 9 + 8] = 0u;
    }
    __syncthreads();

    // ---- conv1 + relu + pool: thread = (g, py, px-pair); rolling rows,
    // channel-group split; windows 16B-aligned -> LDG.128.
    for (int s = tid; s < G * 98; s += THREADS) {
        int g = s / 98, t = s % 98;
        int py = t / 7, pxp = t % 7;
        const float* xg = x + (size_t)(img0 + g) * 3072 + py * 64 + pxp * 4;
        #pragma unroll 1
        for (int cg = 0; cg < 2; cg++) {
            float acc[3][2][4];
            #pragma unroll
            for (int c = 0; c < 3; c++)
                #pragma unroll
                for (int r = 0; r < 2; r++)
                    acc[c][r][0] = acc[c][r][1] = acc[c][r][2] = acc[c][r][3] = 0.0f;

            #pragma unroll 1
            for (int cin = 0; cin < 3; cin++) {
                const float* ib = xg + cin * 1024;
                const float* wb = w1s + (cg * 3 + cin) * 100;
                float rA[8], rB[8];
                LOAD_ROW8(rA, ib);
                LOAD_ROW8(rB, ib + 32);
                C1KY8(rA, rB, 0); LOAD_ROW8(rA, ib + 64);
                C1KY8(rB, rA, 1); LOAD_ROW8(rB, ib + 96);
                C1KY8(rA, rB, 2); LOAD_ROW8(rA, ib + 128);
                C1KY8(rB, rA, 3); LOAD_ROW8(rB, ib + 160);
                C1KY8(rA, rB, 4);
            }
            #pragma unroll
            for (int c = 0; c < 3; c++) {
                int ch = cg * 3 + c;
                float bb = b1s[ch];
                float m0 = fmaxf(fmaxf(acc[c][0][0], acc[c][0][1]),
                                 fmaxf(acc[c][1][0], acc[c][1][1]));
                float m1 = fmaxf(fmaxf(acc[c][0][2], acc[c][0][3]),
                                 fmaxf(acc[c][1][2], acc[c][1][3]));
                float v0 = fmaxf(m0 + bb, 0.0f);
                float v1 = fmaxf(m1 + bb, 0.0f);
                int ridx = ((g * 6 + ch) * 14 + py) * 18 + pxp * 2;
                split_store(p1hi_b, p1lo_b, ridx, v0);
                split_store(p1hi_b, p1lo_b, ridx + 1, v1);
            }
        }
    }
    __syncthreads();

    // ---- conv2 + relu + pool via MMA (exact R15) ----
    {
        int wid = tid >> 5, lane = tid & 31;
        int tq = lane >> 2, tr = lane & 3;
        const uint32_t* s2u = (const uint32_t*)g_s2bf;   // [ch][120 u32]

        for (int u = wid; u < 56; u += 8) {
            int img = u / 7, tp = u % 7;
            float de[4] = {0, 0, 0, 0}, dz[4] = {0, 0, 0, 0};

            int v = tp * 8 + tq;
            int q = v >> 1, dy = v & 1;
            if (q >= 25) { q = 0; dy = 0; }
            int Y = q / 5, X = q % 5;
            int oy = 2 * Y + dy;
            int oxe = 2 * X;

            #pragma unroll
            for (int ks = 0; ks < 15; ks++) {
                const int m0 = 2 * ks, m1 = 2 * ks + 1;
                const int cin0 = m0 / 5, ky0 = m0 % 5;
                const int cin1 = m1 / 5, ky1 = m1 % 5;
                uint32_t A0 = __ldg(s2u + tq * 120 + ks * 8 + tr);
                uint32_t A1 = __ldg(s2u + (tq + 8) * 120 + ks * 8 + tr);
                uint32_t A2 = __ldg(s2u + tq * 120 + ks * 8 + tr + 4);
                uint32_t A3 = __ldg(s2u + (tq + 8) * 120 + ks * 8 + tr + 4);

                int r0 = ((img * 6 + cin0) * 14 + (oy + ky0)) * 18;
                int r1 = ((img * 6 + cin1) * 14 + (oy + ky1)) * 18;
                int ce = oxe + 2 * tr;
                uint32_t e0h = p1hi_u[(r0 + ce) >> 1];
                uint32_t e1h = p1hi_u[(r1 + ce) >> 1];
                uint32_t e0l = p1lo_u[(r0 + ce) >> 1];
                uint32_t e1l = p1lo_u[(r1 + ce) >> 1];
                mma_bf16(de, A0, A1, A2, A3, e0h, e1h);
                mma_bf16(de, A0, A1, A2, A3, e0l, e1l);
                uint32_t x0h = p1hi_u[((r0 + ce) >> 1) + 1];
                uint32_t x1h = p1hi_u[((r1 + ce) >> 1) + 1];
                uint32_t x0l = p1lo_u[((r0 + ce) >> 1) + 1];
                uint32_t x1l = p1lo_u[((r1 + ce) >> 1) + 1];
                mma_bf16(dz, A0, A1, A2, A3, prmt5432(e0h, x0h), prmt5432(e1h, x1h));
                mma_bf16(dz, A0, A1, A2, A3, prmt5432(e0l, x0l), prmt5432(e1l, x1l));
            }

            int qq = tp * 4 + tr;
            if (qq < 25) {
                float sc = g_cs2;
                float m0 = fmaxf(fmaxf(de[0], de[1]), fmaxf(dz[0], dz[1]));
                float m1 = fmaxf(fmaxf(de[2], de[3]), fmaxf(dz[2], dz[3]));
                float h0 = fmaxf(fmaf(sc, m0, b2s[tq]), 0.0f);
                float h1 = fmaxf(fmaf(sc, m1, b2s[tq + 8]), 0.0f);
                split_store(h2hi_b, h2lo_b, img * 400 + tq * 25 + qq, h0);
                split_store(h2hi_b, h2lo_b, img * 400 + (tq + 8) * 25 + qq, h1);
            }
        }
    }
    __syncthreads();

    // ---- fc1 via MMA (exact R15) ----
    {
        int wid = tid >> 5, lane = tid & 31;
        int tq = lane >> 2, tr = lane & 3;
        const uint32_t* s1u = (const uint32_t*)g_s1bf;   // [j][200 u32]

        for (int nt = wid; nt < 15; nt += 8) {
            float d[4] = {0, 0, 0, 0};
            int j = nt * 8 + tq;
            #pragma unroll 5
            for (int ks = 0; ks < 25; ks++) {
                uint32_t a0 = h2hi_u[tq * 200 + ks * 8 + tr];
                uint32_t a2 = h2hi_u[tq * 200 + ks * 8 + tr + 4];
                uint32_t l0 = h2lo_u[tq * 200 + ks * 8 + tr];
                uint32_t l2 = h2lo_u[tq * 200 + ks * 8 + tr + 4];
                uint32_t B0 = __ldg(s1u + j * 200 + ks * 8 + tr);
                uint32_t B1 = __ldg(s1u + j * 200 + ks * 8 + tr + 4);
                mma_bf16(d, a0, 0u, a2, 0u, B0, B1);
                mma_bf16(d, l0, 0u, l2, 0u, B0, B1);
            }
            int jc = nt * 8 + 2 * tr;
            float sc = g_fscale[0];
            a1[tq * 120 + jc]     = fmaxf(fmaf(sc, d[0], __ldg(fb1 + jc)), 0.0f);
            a1[tq * 120 + jc + 1] = fmaxf(fmaf(sc, d[1], __ldg(fb1 + jc + 1)), 0.0f);
        }
    }
    __syncthreads();

    // ---- fc2 scalar XOR ----
    if (tid < 168) {
        int half = tid & 1, j = tid >> 1;
        const float* hg = a1 + half * 4 * 120;
        const float* wr = fw2 + j * 120;
        float acc[4] = {0, 0, 0, 0};
        for (int k = 0; k < 120; k += 4) {
            float4 w = __ldg((const float4*)(wr + k));
            unsigned sx = __float_as_uint(w.x) & 0x80000000u;
            unsigned sy = __float_as_uint(w.y) & 0x80000000u;
            unsigned sz = __float_as_uint(w.z) & 0x80000000u;
            unsigned sw = __float_as_uint(w.w) & 0x80000000u;
            #pragma unroll
            for (int i = 0; i < 4; i++) {
                float4 h = *(const float4*)(hg + i * 120 + k);
                acc[i] += __uint_as_float(__float_as_uint(h.x) ^ sx);
                acc[i] += __uint_as_float(__float_as_uint(h.y) ^ sy);
                acc[i] += __uint_as_float(__float_as_uint(h.z) ^ sz);
                acc[i] += __uint_as_float(__float_as_uint(h.w) ^ sw);
            }
        }
        float sc = g_fscale[1];
        float bb = fb2[j];
        #pragma unroll
        for (int i = 0; i < 4; i++)
            a2v[(half * 4 + i) * 84 + j] = fmaxf(fmaf(sc, acc[i], bb), 0.0f);
    }
    __syncthreads();

    // ---- fc3 scalar XOR ----
    if (tid < G * 10) {
        int g = tid / 10, j = tid % 10;
        const float* ag = a2v + g * 84;
        const float* wr = fw3 + j * 84;
        float acc = 0.0f;
        for (int k = 0; k < 84; k += 4) {
            float4 w = __ldg((const float4*)(wr + k));
            float4 h = *(const float4*)(ag + k);
            acc += __uint_as_float(__float_as_uint(h.x) ^ (__float_as_uint(w.x) & 0x80000000u));
            acc += __uint_as_float(__float_as_uint(h.y) ^ (__float_as_uint(w.y) & 0x80000000u));
            acc += __uint_as_float(__float_as_uint(h.z) ^ (__float_as_uint(w.z) & 0x80000000u));
            acc += __uint_as_float(__float_as_uint(h.w) ^ (__float_as_uint(w.w) & 0x80000000u));
        }
        out[(size_t)(img0 + g) * 10 + j] = fmaf(g_fscale[2], acc, fb3[j]);
    }
}

extern "C" void kernel_launch(void* const* d_in, const int* in_sizes, int n_in,
                              void* d_out, int out_size) {
    const float* x   = (const float*)d_in[0];
    const float* w1  = (const float*)d_in[1];
    const float* b1  = (const float*)d_in[2];
    const float* w2  = (const float*)d_in[3];
    const float* b2  = (const float*)d_in[4];
    const float* fw1 = (const float*)d_in[5];
    const float* fb1 = (const float*)d_in[6];
    const float* fw2 = (const float*)d_in[7];
    const float* fb2 = (const float*)d_in[8];
    const float* fw3 = (const float*)d_in[9];
    const float* fb3 = (const float*)d_in[10];
    float* out = (float*)d_out;

    // smem: 960+672+600+8+16+1600+1600+6048+6048 = 17552 floats = 70,208 B
    const int smem_bytes = 17552 * (int)sizeof(float);
    cudaFuncSetAttribute(fused_kernel, cudaFuncAttributeMaxDynamicSharedMemorySize,
                         smem_bytes);

    binarize_kernel<<<5, 256>>>(w1, w2, fw1, fw2, fw3);
    fused_kernel<<<NBLK, THREADS, smem_bytes>>>(x, fw2, fw3,
                                                b1, b2, fb1, fb2, fb3, out);
}